// round 3
// baseline (speedup 1.0000x reference)
#include <cuda_runtime.h>
#include <cuda_fp16.h>
#include <mma.h>

using namespace nvcuda;

#define D       128
#define D4      32
#define N_MAX   100000
#define E_MAX   3200000
#define EPSV    1e-5f
#define SCAN_B  1024

// ---------------- scratch (static device globals) --------------------------
__device__ int    g_deg[N_MAX];
__device__ int    g_row[N_MAX + 1];
__device__ int    g_cur[N_MAX];
__device__ int    g_csr[E_MAX];
__device__ int    g_part[256];
__device__ __half g_featH[(size_t)N_MAX * D];
__device__ __half g_meanH[(size_t)N_MAX * D];
__device__ __half g_WH[D * D];
__device__ float  g_h[(size_t)N_MAX * D];
__device__ float  g_colsum[D];
__device__ float  g_colsum2[D];
__device__ float  g_scale[D];
__device__ float  g_shift[D];

// ---------------- 1. zero accumulators -------------------------------------
__global__ void zero_kernel(int n) {
    int i = blockIdx.x * blockDim.x + threadIdx.x;
    if (i < n) g_deg[i] = 0;
    if (i < D) { g_colsum[i] = 0.f; g_colsum2[i] = 0.f; }
}

// ---------------- 2. fused prep: hist + feature->fp16 + W->fp16 ------------
__global__ void prep_kernel(const int* __restrict__ dst, int e,
                            const float4* __restrict__ feat, int tot8,
                            const float4* __restrict__ W,
                            int histB, int halfB) {
    int b = blockIdx.x, tid = threadIdx.x;
    if (b < histB) {
        int base = (b * 256 + tid) * 4;
        if (base + 3 < e) {
            int4 d = *(const int4*)(dst + base);
            atomicAdd(&g_deg[d.x], 1);
            atomicAdd(&g_deg[d.y], 1);
            atomicAdd(&g_deg[d.z], 1);
            atomicAdd(&g_deg[d.w], 1);
        } else {
            for (int j = base; j < e; j++) atomicAdd(&g_deg[dst[j]], 1);
        }
    } else if (b < histB + halfB) {
        int i = (b - histB) * 256 + tid;           // one per 8 floats
        if (i < tot8) {
            float4 a = feat[2 * i], c = feat[2 * i + 1];
            __half2 h0 = __floats2half2_rn(a.x, a.y);
            __half2 h1 = __floats2half2_rn(a.z, a.w);
            __half2 h2 = __floats2half2_rn(c.x, c.y);
            __half2 h3 = __floats2half2_rn(c.z, c.w);
            uint4 o;
            o.x = *(unsigned*)&h0; o.y = *(unsigned*)&h1;
            o.z = *(unsigned*)&h2; o.w = *(unsigned*)&h3;
            ((uint4*)g_featH)[i] = o;
        }
    } else {
        int i = (b - histB - halfB) * 256 + tid;   // one per 8 W floats
        if (i < D * D / 8) {
            float4 a = W[2 * i], c = W[2 * i + 1];
            __half2 h0 = __floats2half2_rn(a.x, a.y);
            __half2 h1 = __floats2half2_rn(a.z, a.w);
            __half2 h2 = __floats2half2_rn(c.x, c.y);
            __half2 h3 = __floats2half2_rn(c.z, c.w);
            uint4 o;
            o.x = *(unsigned*)&h0; o.y = *(unsigned*)&h1;
            o.z = *(unsigned*)&h2; o.w = *(unsigned*)&h3;
            ((uint4*)g_WH)[i] = o;
        }
    }
}

// ---------------- 3a. per-block sums of deg ---------------------------------
__global__ void scanA_kernel(int n) {
    __shared__ int ws[32];
    int i = blockIdx.x * SCAN_B + threadIdx.x;
    int v = (i < n) ? g_deg[i] : 0;
    #pragma unroll
    for (int off = 16; off > 0; off >>= 1) v += __shfl_down_sync(0xffffffffu, v, off);
    int lane = threadIdx.x & 31, wid = threadIdx.x >> 5;
    if (lane == 0) ws[wid] = v;
    __syncthreads();
    if (wid == 0) {
        int s = (lane < SCAN_B / 32) ? ws[lane] : 0;
        #pragma unroll
        for (int off = 16; off > 0; off >>= 1) s += __shfl_down_sync(0xffffffffu, s, off);
        if (lane == 0) g_part[blockIdx.x] = s;
    }
}

// ---------------- 3b. exclusive scan of partials (<=128) --------------------
__global__ void scanB_kernel(int nb, int n) {
    __shared__ int ws[4];
    int lane = threadIdx.x & 31, wid = threadIdx.x >> 5;
    int v = (threadIdx.x < nb) ? g_part[threadIdx.x] : 0;
    int incl = v;
    #pragma unroll
    for (int off = 1; off < 32; off <<= 1) {
        int t = __shfl_up_sync(0xffffffffu, incl, off);
        if (lane >= off) incl += t;
    }
    if (lane == 31) ws[wid] = incl;
    __syncthreads();
    int woff = 0;
    for (int w = 0; w < wid; w++) woff += ws[w];
    if (threadIdx.x < nb) g_part[threadIdx.x] = woff + incl - v;
    if (threadIdx.x == 127) g_row[n] = woff + incl;
}

// ---------------- 3c. apply: local scan + block offset ----------------------
__global__ void scanC_kernel(int n) {
    __shared__ int ws[32];
    int i = blockIdx.x * SCAN_B + threadIdx.x;
    int lane = threadIdx.x & 31, wid = threadIdx.x >> 5;
    int v = (i < n) ? g_deg[i] : 0;
    int incl = v;
    #pragma unroll
    for (int off = 1; off < 32; off <<= 1) {
        int t = __shfl_up_sync(0xffffffffu, incl, off);
        if (lane >= off) incl += t;
    }
    if (lane == 31) ws[wid] = incl;
    __syncthreads();
    if (wid == 0) {
        int s = ws[lane];
        #pragma unroll
        for (int off = 1; off < 32; off <<= 1) {
            int t = __shfl_up_sync(0xffffffffu, s, off);
            if (lane >= off) s += t;
        }
        ws[lane] = s;
    }
    __syncthreads();
    int woff = wid ? ws[wid - 1] : 0;
    int excl = g_part[blockIdx.x] + woff + incl - v;
    if (i < n) { g_row[i] = excl; g_cur[i] = excl; }
}

// ---------------- 4. scatter edges into CSR (int4) --------------------------
__global__ void scatter_kernel(const int* __restrict__ src,
                               const int* __restrict__ dst, int e) {
    int base = (blockIdx.x * blockDim.x + threadIdx.x) * 4;
    if (base + 3 < e) {
        int4 d = *(const int4*)(dst + base);
        int4 s = *(const int4*)(src + base);
        g_csr[atomicAdd(&g_cur[d.x], 1)] = s.x;
        g_csr[atomicAdd(&g_cur[d.y], 1)] = s.y;
        g_csr[atomicAdd(&g_cur[d.z], 1)] = s.z;
        g_csr[atomicAdd(&g_cur[d.w], 1)] = s.w;
    } else {
        for (int j = base; j < e; j++)
            g_csr[atomicAdd(&g_cur[dst[j]], 1)] = src[j];
    }
}

// ---------------- 5. per-node mean aggregation (1 warp/node, fp16 in/out) ---
__global__ void gather_mean_kernel(int n) {
    int gw   = (blockIdx.x * blockDim.x + threadIdx.x) >> 5;
    int lane = threadIdx.x & 31;
    if (gw >= n) return;
    int s = g_row[gw], e = g_row[gw + 1];
    const uint2* F = (const uint2*)g_featH;            // 4 halfs per lane
    float a0 = 0.f, a1 = 0.f, a2 = 0.f, a3 = 0.f;
    #pragma unroll 4
    for (int i = s; i < e; i++) {
        int sr = g_csr[i];                              // broadcast
        uint2 v = __ldg(&F[(size_t)sr * 32 + lane]);    // 256B coalesced / warp
        float2 f0 = __half22float2(*(__half2*)&v.x);
        float2 f1 = __half22float2(*(__half2*)&v.y);
        a0 += f0.x; a1 += f0.y; a2 += f1.x; a3 += f1.y;
    }
    float inv = 1.f / fmaxf((float)(e - s), 1.f);
    __half2 o0 = __floats2half2_rn(a0 * inv, a1 * inv);
    __half2 o1 = __floats2half2_rn(a2 * inv, a3 * inv);
    uint2 o; o.x = *(unsigned*)&o0; o.y = *(unsigned*)&o1;
    ((uint2*)g_meanH)[(size_t)gw * 32 + lane] = o;
}

// ---------------- 6. wmma GEMM h = mean @ W + b, fused column stats ---------
// block = 256 thr (8 warps), tile = 64 rows x 128 cols
// smem: [0,32K) sW (fp16) aliased later by sH (fp32); [32K,48K) sA; [48K,49K) stats
__global__ void gemm_kernel(const float* __restrict__ bias, int n) {
    extern __shared__ char smem[];
    __half* sW = (__half*)smem;                 // 128x128 fp16
    __half* sA = (__half*)(smem + 32768);       // 64x128 fp16
    float*  sH = (float*)smem;                  // 64x128 fp32 (aliases sW)
    float*  s_sum  = (float*)(smem + 49152);
    float*  s_sum2 = (float*)(smem + 49152 + 512);

    int tid = threadIdx.x;
    int row0 = blockIdx.x * 64;

    #pragma unroll
    for (int t = tid; t < D * D / 8; t += 256)
        ((uint4*)sW)[t] = ((const uint4*)g_WH)[t];
    uint4 z4; z4.x = z4.y = z4.z = z4.w = 0u;
    #pragma unroll
    for (int t = tid; t < 64 * 16; t += 256) {   // 16 uint4 per row
        int r = t >> 4, c = t & 15;
        ((uint4*)sA)[t] = (row0 + r < n) ? ((const uint4*)g_meanH)[(size_t)(row0 + r) * 16 + c] : z4;
    }
    if (tid < D) { s_sum[tid] = 0.f; s_sum2[tid] = 0.f; }
    __syncthreads();

    int wid = tid >> 5, wr = wid >> 1, wc = wid & 1;
    wmma::fragment<wmma::accumulator, 16, 16, 16, float> acc[4];
    #pragma unroll
    for (int j = 0; j < 4; j++) wmma::fill_fragment(acc[j], 0.f);

    #pragma unroll
    for (int k = 0; k < D; k += 16) {
        wmma::fragment<wmma::matrix_a, 16, 16, 16, __half, wmma::row_major> fa;
        wmma::load_matrix_sync(fa, sA + (wr * 16) * D + k, D);
        #pragma unroll
        for (int j = 0; j < 4; j++) {
            wmma::fragment<wmma::matrix_b, 16, 16, 16, __half, wmma::row_major> fb;
            wmma::load_matrix_sync(fb, sW + k * D + wc * 64 + j * 16, D);
            wmma::mma_sync(acc[j], fa, fb, acc[j]);
        }
    }
    __syncthreads();                              // all reads of sW done
    #pragma unroll
    for (int j = 0; j < 4; j++)
        wmma::store_matrix_sync(sH + (wr * 16) * D + wc * 64 + j * 16, acc[j], D,
                                wmma::mem_row_major);
    __syncthreads();

    // epilogue: bias + write g_h + stats. thread: col group cg (x4), rows rg*8..+7
    int cg = tid & 31, rg = tid >> 5;
    float4 bb = ((const float4*)bias)[cg];
    float ls0=0.f, ls1=0.f, ls2=0.f, ls3=0.f;
    float lq0=0.f, lq1=0.f, lq2=0.f, lq3=0.f;
    #pragma unroll
    for (int i = 0; i < 8; i++) {
        int r = row0 + rg * 8 + i;
        if (r < n) {
            float4 h = *(float4*)&sH[(rg * 8 + i) * D + cg * 4];
            float4 o;
            o.x = h.x + bb.x; o.y = h.y + bb.y;
            o.z = h.z + bb.z; o.w = h.w + bb.w;
            ((float4*)g_h)[(size_t)r * D4 + cg] = o;
            ls0 += o.x; ls1 += o.y; ls2 += o.z; ls3 += o.w;
            lq0 += o.x*o.x; lq1 += o.y*o.y; lq2 += o.z*o.z; lq3 += o.w*o.w;
        }
    }
    atomicAdd(&s_sum[4*cg+0], ls0);  atomicAdd(&s_sum[4*cg+1], ls1);
    atomicAdd(&s_sum[4*cg+2], ls2);  atomicAdd(&s_sum[4*cg+3], ls3);
    atomicAdd(&s_sum2[4*cg+0], lq0); atomicAdd(&s_sum2[4*cg+1], lq1);
    atomicAdd(&s_sum2[4*cg+2], lq2); atomicAdd(&s_sum2[4*cg+3], lq3);
    __syncthreads();
    if (tid < D) {
        atomicAdd(&g_colsum[tid],  s_sum[tid]);
        atomicAdd(&g_colsum2[tid], s_sum2[tid]);
    }
}

// ---------------- 7. fold stats into scale/shift -----------------------------
__global__ void params_kernel(const float* __restrict__ gamma,
                              const float* __restrict__ beta, float inv_n) {
    int j = threadIdx.x;
    float mu  = g_colsum[j]  * inv_n;
    float var = g_colsum2[j] * inv_n - mu * mu;
    float sc  = gamma[j] * rsqrtf(var + EPSV);
    g_scale[j] = sc;
    g_shift[j] = beta[j] - mu * sc;
}

// ---------------- 8. finalize: out = feature + relu(h*scale + shift) --------
__global__ void finalize_kernel(const float4* __restrict__ feat,
                                float4* __restrict__ out, int n4) {
    __shared__ float4 ssc[D4], ssh[D4];
    if (threadIdx.x < D4) {
        ssc[threadIdx.x] = ((const float4*)g_scale)[threadIdx.x];
        ssh[threadIdx.x] = ((const float4*)g_shift)[threadIdx.x];
    }
    __syncthreads();
    const float4* H4 = (const float4*)g_h;
    for (int i = blockIdx.x * blockDim.x + threadIdx.x; i < n4;
         i += gridDim.x * blockDim.x) {
        int c = i & (D4 - 1);
        float4 h = H4[i], f = feat[i], sc = ssc[c], sh = ssh[c];
        float4 o;
        o.x = f.x + fmaxf(h.x * sc.x + sh.x, 0.f);
        o.y = f.y + fmaxf(h.y * sc.y + sh.y, 0.f);
        o.z = f.z + fmaxf(h.z * sc.z + sh.z, 0.f);
        o.w = f.w + fmaxf(h.w * sc.w + sh.w, 0.f);
        out[i] = o;
    }
}

// ---------------- launch -----------------------------------------------------
extern "C" void kernel_launch(void* const* d_in, const int* in_sizes, int n_in,
                              void* d_out, int out_size) {
    const float* feature = (const float*)d_in[0];
    const int*   src     = (const int*)d_in[1];
    const int*   dst     = (const int*)d_in[2];
    const float* W       = (const float*)d_in[3];
    const float* b       = (const float*)d_in[4];
    const float* gamma   = (const float*)d_in[5];
    const float* beta    = (const float*)d_in[6];
    float*       out     = (float*)d_out;

    int n  = in_sizes[0] / D;
    int e  = in_sizes[1];
    int n4 = n * D4;
    int nb = (n + SCAN_B - 1) / SCAN_B;

    int tot8  = n * D / 8;
    int histB = ((e + 3) / 4 + 255) / 256;
    int halfB = (tot8 + 255) / 256;
    int wB    = (D * D / 8 + 255) / 256;

    zero_kernel<<<(n + 255) / 256, 256>>>(n);
    prep_kernel<<<histB + halfB + wB, 256>>>(dst, e, (const float4*)feature, tot8,
                                             (const float4*)W, histB, halfB);
    scanA_kernel<<<nb, SCAN_B>>>(n);
    scanB_kernel<<<1, 128>>>(nb, n);
    scanC_kernel<<<nb, SCAN_B>>>(n);
    scatter_kernel<<<((e + 3) / 4 + 255) / 256, 256>>>(src, dst, e);

    gather_mean_kernel<<<(n * 32 + 255) / 256, 256>>>(n);

    static const int GEMM_SMEM = 50176;
    cudaFuncSetAttribute(gemm_kernel, cudaFuncAttributeMaxDynamicSharedMemorySize, GEMM_SMEM);
    gemm_kernel<<<(n + 63) / 64, 256, GEMM_SMEM>>>(b, n);

    params_kernel<<<1, D>>>(gamma, beta, 1.f / (float)n);

    finalize_kernel<<<(n4 + 255) / 256, 256>>>((const float4*)feature, (float4*)out, n4);
}